// round 15
// baseline (speedup 1.0000x reference)
#include <cuda_runtime.h>
#include <cuda_fp16.h>
#include <cstdint>

// ============================================================
// Problem constants
// ============================================================
#define N_NODES 100000
#define H_FEATS 128
#define TILE_M 64
#define N_TILES 1563         // ceil(100000 / 64)
#define PGRID 152            // persistent grid (GB300: 152 SMs)

// P[node][0:128] = h[node] @ W1[0:128,:]   (src half)
// P[node][128:256] = h[node] @ W1[128:256,:] (dst half)
// Stored fp16: 51.2 MB -> L2-resident, halves edge-gather traffic.
__device__ __align__(16) __half g_Ph[(size_t)N_NODES * 256];
__device__ int g_idx_is64;

// ============================================================
// Helpers
// ============================================================
__device__ __forceinline__ uint32_t smem_u32(const void* p) {
    uint32_t a;
    asm("{ .reg .u64 t; cvta.to.shared.u64 t, %1; cvt.u32.u64 %0, t; }"
        : "=r"(a) : "l"(p));
    return a;
}

// mma.sync m16n8k16 fp16 in, fp32 accum (sm_80 baseline PTX; legal on compute_103)
__device__ __forceinline__ void mma_f16(float* c, const uint32_t* a, const uint32_t* b) {
    asm volatile(
        "mma.sync.aligned.m16n8k16.row.col.f32.f16.f16.f32 "
        "{%0,%1,%2,%3}, {%4,%5,%6,%7}, {%8,%9}, {%0,%1,%2,%3};"
        : "+f"(c[0]), "+f"(c[1]), "+f"(c[2]), "+f"(c[3])
        : "r"(a[0]), "r"(a[1]), "r"(a[2]), "r"(a[3]),
          "r"(b[0]), "r"(b[1]));
}

__device__ __forceinline__ uint32_t pack_h2(float x, float y) {
    __half2 h = __floats2half2_rn(x, y);
    return *reinterpret_cast<uint32_t*>(&h);
}

// 16B async copy (L2 -> smem, bypasses L1/RF); src_bytes 0 => zero-fill
__device__ __forceinline__ void cp_async16(uint32_t dst_smem, const void* src, int src_bytes) {
    asm volatile("cp.async.cg.shared.global [%0], [%1], 16, %2;"
                 :: "r"(dst_smem), "l"(src), "r"(src_bytes) : "memory");
}
__device__ __forceinline__ void cp_async_commit() {
    asm volatile("cp.async.commit_group;" ::: "memory");
}
__device__ __forceinline__ void cp_async_wait2() {
    asm volatile("cp.async.wait_group 2;" ::: "memory");
}

// ============================================================
// Kernel A (persistent): P[node][0:256] = h[node] @ [W1a | W1b].
// grid = PGRID, 512 threads, 16 warps (4M x 4N), warp tile 16x64.
// Tiles of 64 nodes; A triple-buffered via cp.async with 2-tile lookahead;
// B (all of W1, fp16 k-pairs, paired for LDS.64) staged ONCE per CTA.
// Epilogue reuses the just-consumed A buffer.
//
// A buffer: Af[row][k] fp32, pitch LDAF=136 floats (LDS.64 per-phase
//   conflict-free: banks 8g+2tg even-unique within 16-lane phase).
// B: Bq[rq][n] uint2 = { pack(W[2p0][n],W[2p0+1][n]),
//                        pack(W[2p1][n],W[2p1+1][n]) },
//   rq = ks*4+tg, p0 = 8ks+tg, p1 = p0+4; pitch LDBQ=260 uint2
//   (2080B -> bank-pairs 2g+8tg+const, all-32-banks conflict-free).
// Epilogue Po: pitch LDOW=132 words (banks 4g+tg, bijective).
// ============================================================
#define LDAF 136   // floats per Af row
#define LDBQ 260   // uint2 per Bq row
#define LDOW 132   // words per Po row
#define AF_FLOATS (TILE_M * LDAF)                   // 8704 floats = 34816 B
#define BQ_BYTES (32 * LDBQ * 8)                    // 66560
#define SMEM_BYTES (3 * AF_FLOATS * 4 + BQ_BYTES)   // 104448 + 66560 = 171008

__global__ void __launch_bounds__(512, 1)
precompute_kernel(const float* __restrict__ h, const float* __restrict__ W1) {
    extern __shared__ float smf[];
    float* AfBase = smf;
    uint2* Bq = reinterpret_cast<uint2*>(smf + 3 * AF_FLOATS);

    const int tid = threadIdx.x;
    const uint32_t Af_u[3] = { smem_u32(AfBase), smem_u32(AfBase + AF_FLOATS),
                               smem_u32(AfBase + 2 * AF_FLOATS) };
    float* const Af[3] = { AfBase, AfBase + AF_FLOATS, AfBase + 2 * AF_FLOATS };

    // --- Prologue: issue cp.async for tiles t0, t0+PGRID into buf0, buf1 ---
    #pragma unroll
    for (int pre = 0; pre < 2; pre++) {
        int tt = blockIdx.x + pre * PGRID;
        if (tt < N_TILES) {
            long base = (long)tt * TILE_M;
            #pragma unroll
            for (int i = tid; i < TILE_M * 32; i += 512) {
                int r = i >> 5, c4 = i & 31;
                long node = base + r;
                int sz = (node < N_NODES) ? 16 : 0;
                cp_async16(Af_u[pre] + (uint32_t)(r * LDAF + c4 * 4) * 4,
                           h + node * 128 + c4 * 4, sz);
            }
        }
        cp_async_commit();
    }

    // --- Stage B once: paired k-fragments for LDS.64 mainloop loads ---
    // i over 32 rq-rows x 64 col-quads = 2048
    #pragma unroll
    for (int i = tid; i < 32 * 64; i += 512) {
        int rq = i >> 6;             // 0..31
        int n4 = i & 63;             // col quad over n 0..255
        int hh = n4 >> 5;            // W1 half
        int colq = (n4 & 31) * 4;    // col within half, 0..124
        int p0 = (rq >> 2) * 8 + (rq & 3);
        int p1 = p0 + 4;
        const float* W00 = W1 + (size_t)(hh * 128 + 2 * p0) * 128 + colq;
        const float* W10 = W1 + (size_t)(hh * 128 + 2 * p1) * 128 + colq;
        float4 v00 = *reinterpret_cast<const float4*>(W00);
        float4 v01 = *reinterpret_cast<const float4*>(W00 + 128);
        float4 v10 = *reinterpret_cast<const float4*>(W10);
        float4 v11 = *reinterpret_cast<const float4*>(W10 + 128);
        int nb = hh * 128 + colq;
        uint4 lo, hi;
        lo.x = pack_h2(v00.x, v01.x); lo.y = pack_h2(v10.x, v11.x);
        lo.z = pack_h2(v00.y, v01.y); lo.w = pack_h2(v10.y, v11.y);
        hi.x = pack_h2(v00.z, v01.z); hi.y = pack_h2(v10.z, v11.z);
        hi.z = pack_h2(v00.w, v01.w); hi.w = pack_h2(v10.w, v11.w);
        *reinterpret_cast<uint4*>(&Bq[rq * LDBQ + nb]) = lo;
        *reinterpret_cast<uint4*>(&Bq[rq * LDBQ + nb + 2]) = hi;
    }

    // --- Warp layout: 16 warps = 4 (M, 16 rows each) x 4 (N, 64 each) ---
    const int wid = tid >> 5, lane = tid & 31;
    const int g = lane >> 2, tg = lane & 3;
    const int wm = wid & 3, wn = wid >> 2;
    const int m0 = wm * 16, n0 = wn * 64;

    int cur = 0;
    for (int t = blockIdx.x; t < N_TILES; t += PGRID) {
        // --- Issue prefetch of tile t+2*PGRID into buf[(cur+2)%3] ---
        int tn = t + 2 * PGRID;
        if (tn < N_TILES) {
            int nb = cur + 2; if (nb >= 3) nb -= 3;
            long base = (long)tn * TILE_M;
            #pragma unroll
            for (int i = tid; i < TILE_M * 32; i += 512) {
                int r = i >> 5, c4 = i & 31;
                long node = base + r;
                int sz = (node < N_NODES) ? 16 : 0;
                cp_async16(Af_u[nb] + (uint32_t)(r * LDAF + c4 * 4) * 4,
                           h + node * 128 + c4 * 4, sz);
            }
        }
        cp_async_commit();

        // --- Wait for tile t's data (allow 2 newest groups pending) ---
        cp_async_wait2();
        __syncthreads();

        // --- Mainloop on Af[cur] ---
        const float* A = Af[cur];
        float acc[8][4];
        #pragma unroll
        for (int nt = 0; nt < 8; nt++)
            #pragma unroll
            for (int j = 0; j < 4; j++)
                acc[nt][j] = 0.0f;

        #pragma unroll
        for (int ks = 0; ks < 8; ks++) {
            const int k2 = ks * 16 + 2 * tg;
            const int row = m0 + g;
            float2 f0 = *reinterpret_cast<const float2*>(&A[row * LDAF + k2]);
            float2 f1 = *reinterpret_cast<const float2*>(&A[(row + 8) * LDAF + k2]);
            float2 f2 = *reinterpret_cast<const float2*>(&A[row * LDAF + k2 + 8]);
            float2 f3 = *reinterpret_cast<const float2*>(&A[(row + 8) * LDAF + k2 + 8]);
            uint32_t a[4];
            a[0] = pack_h2(f0.x, f0.y);
            a[1] = pack_h2(f1.x, f1.y);
            a[2] = pack_h2(f2.x, f2.y);
            a[3] = pack_h2(f3.x, f3.y);
            const uint2* brow = &Bq[(ks * 4 + tg) * LDBQ];
            #pragma unroll
            for (int nt = 0; nt < 8; nt++) {
                uint2 bq = brow[n0 + nt * 8 + g];
                uint32_t b[2] = { bq.x, bq.y };
                mma_f16(acc[nt], a, b);
            }
        }

        __syncthreads();  // all warps done reading Af[cur]

        // --- Epilogue: acc -> fp16 into (freed) Af[cur], then copy out ---
        uint32_t* Pw = reinterpret_cast<uint32_t*>(Af[cur]);
        {
            const int row0 = m0 + g;
            #pragma unroll
            for (int nt = 0; nt < 8; nt++) {
                const int colw = (n0 + nt * 8 + tg * 2) >> 1;
                Pw[row0 * LDOW + colw] = pack_h2(acc[nt][0], acc[nt][1]);
                Pw[(row0 + 8) * LDOW + colw] = pack_h2(acc[nt][2], acc[nt][3]);
            }
        }
        __syncthreads();

        const long tbase = (long)t * TILE_M;
        #pragma unroll
        for (int i = tid; i < TILE_M * 32; i += 512) {
            int r = i >> 5, c = i & 31;
            long node = tbase + r;
            if (node < N_NODES) {
                uint4 v = *reinterpret_cast<const uint4*>(&Pw[r * LDOW + c * 4]);
                *reinterpret_cast<uint4*>(g_Ph + node * 256 + c * 8) = v;
            }
        }
        __syncthreads();   // copy-out done before buf[cur] is re-targeted

        cur = cur + 1; if (cur >= 3) cur = 0;
    }
}

// ============================================================
// Detector: are src/dst int64 (high 32-bit words all zero) or int32?
// ============================================================
__global__ void detect_kernel(const int* __restrict__ src32) {
    if (threadIdx.x == 0) {
        int any = 0;
        #pragma unroll 4
        for (int i = 0; i < 64; i++) any |= src32[2 * i + 1];
        g_idx_is64 = (any == 0) ? 1 : 0;
    }
}

// ============================================================
// Kernel B: 16 lanes per edge, 4 edges per 16-lane group per iter
// (8 edges in flight per warp; 8 outstanding LDG.128 gathers, L1-bypass).
// score[e] = b2 + sum_n relu(P[src][n] + P[dst][128+n] + b1[n]) * W2[n]
// ============================================================
__device__ __forceinline__ float edge_partial(
    const uint4& av, const uint4& bv,
    const float4& b1lo, const float4& b1hi,
    const float4& w2lo, const float4& w2hi) {
    const __half2* ah = reinterpret_cast<const __half2*>(&av);
    const __half2* bh = reinterpret_cast<const __half2*>(&bv);
    float2 fa0 = __half22float2(ah[0]), fb0 = __half22float2(bh[0]);
    float2 fa1 = __half22float2(ah[1]), fb1 = __half22float2(bh[1]);
    float2 fa2 = __half22float2(ah[2]), fb2 = __half22float2(bh[2]);
    float2 fa3 = __half22float2(ah[3]), fb3 = __half22float2(bh[3]);
    float x0 = fmaxf(fa0.x + fb0.x + b1lo.x, 0.0f);
    float x1 = fmaxf(fa0.y + fb0.y + b1lo.y, 0.0f);
    float x2 = fmaxf(fa1.x + fb1.x + b1lo.z, 0.0f);
    float x3 = fmaxf(fa1.y + fb1.y + b1lo.w, 0.0f);
    float x4 = fmaxf(fa2.x + fb2.x + b1hi.x, 0.0f);
    float x5 = fmaxf(fa2.y + fb2.y + b1hi.y, 0.0f);
    float x6 = fmaxf(fa3.x + fb3.x + b1hi.z, 0.0f);
    float x7 = fmaxf(fa3.y + fb3.y + b1hi.w, 0.0f);
    return x0 * w2lo.x + x1 * w2lo.y + x2 * w2lo.z + x3 * w2lo.w
         + x4 * w2hi.x + x5 * w2hi.y + x6 * w2hi.z + x7 * w2hi.w;
}

__global__ void __launch_bounds__(256)
edge_kernel(const void* __restrict__ src, const void* __restrict__ dst,
            const float* __restrict__ b1, const float* __restrict__ W2,
            const float* __restrict__ b2, float* __restrict__ out, int E) {
    const int lane = threadIdx.x & 31;
    const int sub = lane >> 4;      // group 0/1 within warp
    const int l16 = lane & 15;
    const int gw = (blockIdx.x * blockDim.x + threadIdx.x) >> 5;
    const int nw = (gridDim.x * blockDim.x) >> 5;
    const int noct = (E + 7) >> 3;  // 8 edges per warp-iter

    const float4 b1lo = reinterpret_cast<const float4*>(b1)[l16 * 2];
    const float4 b1hi = reinterpret_cast<const float4*>(b1)[l16 * 2 + 1];
    const float4 w2lo = reinterpret_cast<const float4*>(W2)[l16 * 2];
    const float4 w2hi = reinterpret_cast<const float4*>(W2)[l16 * 2 + 1];
    const float b2v = b2[0];
    const int is64 = g_idx_is64;
    const long long* src64 = reinterpret_cast<const long long*>(src);
    const long long* dst64 = reinterpret_cast<const long long*>(dst);
    const int* src32 = reinterpret_cast<const int*>(src);
    const int* dst32 = reinterpret_cast<const int*>(dst);

    for (int q = gw; q < noct; q += nw) {
        const int ebase = q * 8 + sub * 4;

        // --- All 8 index loads first ---
        long s[4], d[4];
        #pragma unroll
        for (int j = 0; j < 4; j++) {
            int e = ebase + j;
            if (e < E) {
                if (is64) { s[j] = (long)src64[e]; d[j] = (long)dst64[e]; }
                else      { s[j] = src32[e];       d[j] = dst32[e]; }
            } else { s[j] = 0; d[j] = 0; }
        }

        // --- 8 independent LDG.128 gathers (L1-bypass), back-to-back ---
        uint4 av[4], bv[4];
        #pragma unroll
        for (int j = 0; j < 4; j++) {
            av[j] = __ldcg(reinterpret_cast<const uint4*>(g_Ph + (size_t)s[j] * 256) + l16);
            bv[j] = __ldcg(reinterpret_cast<const uint4*>(g_Ph + (size_t)d[j] * 256 + 128) + l16);
        }

        // --- Compute partials ---
        float acc[4];
        #pragma unroll
        for (int j = 0; j < 4; j++)
            acc[j] = edge_partial(av[j], bv[j], b1lo, b1hi, w2lo, w2hi);

        // --- Shared reduction tree over 16 lanes for all four edges ---
        #pragma unroll
        for (int m = 8; m > 0; m >>= 1) {
            #pragma unroll
            for (int j = 0; j < 4; j++)
                acc[j] += __shfl_xor_sync(0xFFFFFFFFu, acc[j], m);
        }

        if (l16 == 0) {
            #pragma unroll
            for (int j = 0; j < 4; j++) {
                int e = ebase + j;
                if (e < E) out[e] = acc[j] + b2v;
            }
        }
    }
}

// ============================================================
// Launch
// ============================================================
extern "C" void kernel_launch(void* const* d_in, const int* in_sizes, int n_in,
                              void* d_out, int out_size) {
    const float* h   = (const float*)d_in[0];
    const void*  src = d_in[1];
    const void*  dst = d_in[2];
    const float* W1  = (const float*)d_in[3];
    const float* b1  = (const float*)d_in[4];
    const float* W2  = (const float*)d_in[5];
    const float* b2  = (const float*)d_in[6];
    float* out = (float*)d_out;
    const int E = out_size;  // one score per edge
    (void)in_sizes; (void)n_in;

    cudaFuncSetAttribute(precompute_kernel,
                         cudaFuncAttributeMaxDynamicSharedMemorySize, SMEM_BYTES);

    precompute_kernel<<<PGRID, 512, SMEM_BYTES>>>(h, W1);
    detect_kernel<<<1, 32>>>((const int*)src);
    edge_kernel<<<2368, 256>>>(src, dst, b1, W2, b2, out, E);
}

// round 16
// speedup vs baseline: 1.5896x; 1.5896x over previous
#include <cuda_runtime.h>
#include <cuda_fp16.h>
#include <cstdint>

// ============================================================
// Problem constants
// ============================================================
#define N_NODES 100000
#define H_FEATS 128
#define N_TILES 782          // ceil(100000 / 128)
#define PGRID 152            // persistent grid (GB300: 152 SMs)

// P[node][0:128] = h[node] @ W1[0:128,:]   (src half)
// P[node][128:256] = h[node] @ W1[128:256,:] (dst half)
// Stored fp16: 51.2 MB -> L2-resident, halves edge-gather traffic.
__device__ __align__(16) __half g_Ph[(size_t)N_NODES * 256];
__device__ int g_idx_is64;

// ============================================================
// Helpers
// ============================================================
__device__ __forceinline__ uint32_t smem_u32(const void* p) {
    uint32_t a;
    asm("{ .reg .u64 t; cvta.to.shared.u64 t, %1; cvt.u32.u64 %0, t; }"
        : "=r"(a) : "l"(p));
    return a;
}

// mma.sync m16n8k16 fp16 in, fp32 accum (sm_80 baseline PTX; legal on compute_103)
__device__ __forceinline__ void mma_f16(float* c, const uint32_t* a, const uint32_t* b) {
    asm volatile(
        "mma.sync.aligned.m16n8k16.row.col.f32.f16.f16.f32 "
        "{%0,%1,%2,%3}, {%4,%5,%6,%7}, {%8,%9}, {%0,%1,%2,%3};"
        : "+f"(c[0]), "+f"(c[1]), "+f"(c[2]), "+f"(c[3])
        : "r"(a[0]), "r"(a[1]), "r"(a[2]), "r"(a[3]),
          "r"(b[0]), "r"(b[1]));
}

__device__ __forceinline__ uint32_t pack_h2(float x, float y) {
    __half2 h = __floats2half2_rn(x, y);
    return *reinterpret_cast<uint32_t*>(&h);
}

// 16B async copy (L2 -> smem, bypasses L1/RF); src_bytes 0 => zero-fill
__device__ __forceinline__ void cp_async16(uint32_t dst_smem, const void* src, int src_bytes) {
    asm volatile("cp.async.cg.shared.global [%0], [%1], 16, %2;"
                 :: "r"(dst_smem), "l"(src), "r"(src_bytes) : "memory");
}
__device__ __forceinline__ void cp_async_commit() {
    asm volatile("cp.async.commit_group;" ::: "memory");
}
__device__ __forceinline__ void cp_async_wait0() {
    asm volatile("cp.async.wait_group 0;" ::: "memory");
}

// ============================================================
// Kernel A (persistent): P[node][0:256] = h[node] @ [W1a | W1b].
// R14 config: grid = PGRID, 512 threads, 16 warps (4M x 4N), warp tile
// 32x64, M=128 tiles, A double-buffered cp.async, B staged once.
// ONLY change vs R14: B stored as paired uint2 so each b-fragment pair
// is ONE LDS.64 instead of two LDS.32.
//
// A buffer: Af[row][k] fp32, pitch LDAF=136 floats.
// B: Bq[rq][n] uint2 = { pack(W[2p0][n],W[2p0+1][n]),
//                        pack(W[2p1][n],W[2p1+1][n]) },
//   rq = ks*4+tg (0..31), p0 = 8ks+tg, p1 = p0+4; pitch LDBQ=260 uint2.
//   Conflict-check: word = (520*tg + 2g) mod 32 = 8tg+2g, distinct within
//   each 16-lane phase -> conflict-free LDS.64.
// Epilogue Po: pitch LDOW=132 words (banks 4g+tg, bijective).
// ============================================================
#define LDAF 136   // floats per Af row
#define LDBQ 260   // uint2 per Bq row
#define LDOW 132   // words per Po row
#define AF_WORDS (128 * LDAF)                       // 17408 floats = 69632 B
#define BQ_BYTES (32 * LDBQ * 8)                    // 66560
#define SMEM_BYTES (2 * AF_WORDS * 4 + BQ_BYTES)    // 139264 + 66560 = 205824

__global__ void __launch_bounds__(512, 1)
precompute_kernel(const float* __restrict__ h, const float* __restrict__ W1) {
    extern __shared__ float smf[];
    float* Af0 = smf;
    float* Af1 = smf + AF_WORDS;
    uint2* Bq = reinterpret_cast<uint2*>(smf + 2 * AF_WORDS);

    const int tid = threadIdx.x;
    const uint32_t Af_u[2] = { smem_u32(Af0), smem_u32(Af1) };
    float* const Af[2] = { Af0, Af1 };

    // --- Prologue: issue cp.async for tile t0 into buf0 ---
    {
        long base = (long)blockIdx.x * 128;
        #pragma unroll
        for (int i = tid; i < 128 * 32; i += 512) {
            int r = i >> 5, c4 = i & 31;
            long node = base + r;
            int sz = (node < N_NODES) ? 16 : 0;
            cp_async16(Af_u[0] + (uint32_t)(r * LDAF + c4 * 4) * 4,
                       h + node * 128 + c4 * 4, sz);
        }
        cp_async_commit();
    }

    // --- Stage B once: paired k-fragments (one LDS.64 per b-pair) ---
    // i over 32 rq-rows x 64 col-quads = 2048
    #pragma unroll
    for (int i = tid; i < 32 * 64; i += 512) {
        int rq = i >> 6;             // 0..31 : rq = ks*4 + tg
        int n4 = i & 63;             // col quad over n 0..255
        int hh = n4 >> 5;            // W1 half
        int colq = (n4 & 31) * 4;    // col within half, 0..124
        int p0 = (rq >> 2) * 8 + (rq & 3);
        int p1 = p0 + 4;
        const float* W00 = W1 + (size_t)(hh * 128 + 2 * p0) * 128 + colq;
        const float* W10 = W1 + (size_t)(hh * 128 + 2 * p1) * 128 + colq;
        float4 v00 = *reinterpret_cast<const float4*>(W00);
        float4 v01 = *reinterpret_cast<const float4*>(W00 + 128);
        float4 v10 = *reinterpret_cast<const float4*>(W10);
        float4 v11 = *reinterpret_cast<const float4*>(W10 + 128);
        int nb = hh * 128 + colq;
        uint4 lo, hi;
        lo.x = pack_h2(v00.x, v01.x); lo.y = pack_h2(v10.x, v11.x);
        lo.z = pack_h2(v00.y, v01.y); lo.w = pack_h2(v10.y, v11.y);
        hi.x = pack_h2(v00.z, v01.z); hi.y = pack_h2(v10.z, v11.z);
        hi.z = pack_h2(v00.w, v01.w); hi.w = pack_h2(v10.w, v11.w);
        *reinterpret_cast<uint4*>(&Bq[rq * LDBQ + nb]) = lo;
        *reinterpret_cast<uint4*>(&Bq[rq * LDBQ + nb + 2]) = hi;
    }
    cp_async_wait0();
    __syncthreads();

    // --- Warp layout: 16 warps = 4 (M) x 4 (N), warp tile 32x64 ---
    const int wid = tid >> 5, lane = tid & 31;
    const int g = lane >> 2, tg = lane & 3;
    const int wm = wid & 3, wn = wid >> 2;
    const int m0 = wm * 32, n0 = wn * 64;

    int cur = 0;
    for (int t = blockIdx.x; t < N_TILES; t += PGRID, cur ^= 1) {
        // --- Prefetch tile t+PGRID into the other buffer ---
        int tn = t + PGRID;
        if (tn < N_TILES) {
            long base = (long)tn * 128;
            #pragma unroll
            for (int i = tid; i < 128 * 32; i += 512) {
                int r = i >> 5, c4 = i & 31;
                long node = base + r;
                int sz = (node < N_NODES) ? 16 : 0;
                cp_async16(Af_u[cur ^ 1] + (uint32_t)(r * LDAF + c4 * 4) * 4,
                           h + node * 128 + c4 * 4, sz);
            }
        }
        cp_async_commit();

        // --- Mainloop on Af[cur]: LDS.64 fp32 pairs, pack, MMA ---
        const float* A = Af[cur];
        float acc[2][8][4];
        #pragma unroll
        for (int mt = 0; mt < 2; mt++)
            #pragma unroll
            for (int nt = 0; nt < 8; nt++)
                #pragma unroll
                for (int j = 0; j < 4; j++)
                    acc[mt][nt][j] = 0.0f;

        #pragma unroll
        for (int ks = 0; ks < 8; ks++) {
            const int k2 = ks * 16 + 2 * tg;   // float index of this lane's k-pair
            uint32_t a[2][4];
            #pragma unroll
            for (int mt = 0; mt < 2; mt++) {
                const int row = m0 + mt * 16 + g;
                float2 f0 = *reinterpret_cast<const float2*>(&A[row * LDAF + k2]);
                float2 f1 = *reinterpret_cast<const float2*>(&A[(row + 8) * LDAF + k2]);
                float2 f2 = *reinterpret_cast<const float2*>(&A[row * LDAF + k2 + 8]);
                float2 f3 = *reinterpret_cast<const float2*>(&A[(row + 8) * LDAF + k2 + 8]);
                a[mt][0] = pack_h2(f0.x, f0.y);
                a[mt][1] = pack_h2(f1.x, f1.y);
                a[mt][2] = pack_h2(f2.x, f2.y);
                a[mt][3] = pack_h2(f3.x, f3.y);
            }
            const uint2* brow = &Bq[(ks * 4 + tg) * LDBQ];
            uint32_t b[8][2];
            #pragma unroll
            for (int nt = 0; nt < 8; nt++) {
                uint2 bq = brow[n0 + nt * 8 + g];
                b[nt][0] = bq.x;
                b[nt][1] = bq.y;
            }
            #pragma unroll
            for (int mt = 0; mt < 2; mt++)
                #pragma unroll
                for (int nt = 0; nt < 8; nt++)
                    mma_f16(acc[mt][nt], a[mt], b[nt]);
        }

        __syncthreads();  // all warps done reading Af[cur]

        // --- Epilogue: acc -> fp16 into (freed) Af[cur], then copy out ---
        uint32_t* Pw = reinterpret_cast<uint32_t*>(Af[cur]);
        #pragma unroll
        for (int mt = 0; mt < 2; mt++) {
            const int row0 = m0 + mt * 16 + g;
            #pragma unroll
            for (int nt = 0; nt < 8; nt++) {
                const int colw = (n0 + nt * 8 + tg * 2) >> 1;
                Pw[row0 * LDOW + colw] = pack_h2(acc[mt][nt][0], acc[mt][nt][1]);
                Pw[(row0 + 8) * LDOW + colw] = pack_h2(acc[mt][nt][2], acc[mt][nt][3]);
            }
        }
        __syncthreads();

        const long tbase = (long)t * 128;
        #pragma unroll
        for (int i = tid; i < 128 * 32; i += 512) {
            int r = i >> 5, c = i & 31;
            long node = tbase + r;
            if (node < N_NODES) {
                uint4 v = *reinterpret_cast<const uint4*>(&Pw[r * LDOW + c * 4]);
                *reinterpret_cast<uint4*>(g_Ph + node * 256 + c * 8) = v;
            }
        }

        cp_async_wait0();   // tile t+PGRID landed
        __syncthreads();
    }
}

// ============================================================
// Detector: are src/dst int64 (high 32-bit words all zero) or int32?
// ============================================================
__global__ void detect_kernel(const int* __restrict__ src32) {
    if (threadIdx.x == 0) {
        int any = 0;
        #pragma unroll 4
        for (int i = 0; i < 64; i++) any |= src32[2 * i + 1];
        g_idx_is64 = (any == 0) ? 1 : 0;
    }
}

// ============================================================
// Kernel B (R14 form, plain cached loads): 16 lanes per edge, 4 edges
// per 16-lane group per iter (8 edges in flight per warp).
// score[e] = b2 + sum_n relu(P[src][n] + P[dst][128+n] + b1[n]) * W2[n]
// ============================================================
__device__ __forceinline__ float edge_partial(
    const uint4& av, const uint4& bv,
    const float4& b1lo, const float4& b1hi,
    const float4& w2lo, const float4& w2hi) {
    const __half2* ah = reinterpret_cast<const __half2*>(&av);
    const __half2* bh = reinterpret_cast<const __half2*>(&bv);
    float2 fa0 = __half22float2(ah[0]), fb0 = __half22float2(bh[0]);
    float2 fa1 = __half22float2(ah[1]), fb1 = __half22float2(bh[1]);
    float2 fa2 = __half22float2(ah[2]), fb2 = __half22float2(bh[2]);
    float2 fa3 = __half22float2(ah[3]), fb3 = __half22float2(bh[3]);
    float x0 = fmaxf(fa0.x + fb0.x + b1lo.x, 0.0f);
    float x1 = fmaxf(fa0.y + fb0.y + b1lo.y, 0.0f);
    float x2 = fmaxf(fa1.x + fb1.x + b1lo.z, 0.0f);
    float x3 = fmaxf(fa1.y + fb1.y + b1lo.w, 0.0f);
    float x4 = fmaxf(fa2.x + fb2.x + b1hi.x, 0.0f);
    float x5 = fmaxf(fa2.y + fb2.y + b1hi.y, 0.0f);
    float x6 = fmaxf(fa3.x + fb3.x + b1hi.z, 0.0f);
    float x7 = fmaxf(fa3.y + fb3.y + b1hi.w, 0.0f);
    return x0 * w2lo.x + x1 * w2lo.y + x2 * w2lo.z + x3 * w2lo.w
         + x4 * w2hi.x + x5 * w2hi.y + x6 * w2hi.z + x7 * w2hi.w;
}

__global__ void __launch_bounds__(256)
edge_kernel(const void* __restrict__ src, const void* __restrict__ dst,
            const float* __restrict__ b1, const float* __restrict__ W2,
            const float* __restrict__ b2, float* __restrict__ out, int E) {
    const int lane = threadIdx.x & 31;
    const int sub = lane >> 4;      // group 0/1 within warp
    const int l16 = lane & 15;
    const int gw = (blockIdx.x * blockDim.x + threadIdx.x) >> 5;
    const int nw = (gridDim.x * blockDim.x) >> 5;
    const int noct = (E + 7) >> 3;  // 8 edges per warp-iter

    const float4 b1lo = reinterpret_cast<const float4*>(b1)[l16 * 2];
    const float4 b1hi = reinterpret_cast<const float4*>(b1)[l16 * 2 + 1];
    const float4 w2lo = reinterpret_cast<const float4*>(W2)[l16 * 2];
    const float4 w2hi = reinterpret_cast<const float4*>(W2)[l16 * 2 + 1];
    const float b2v = b2[0];
    const int is64 = g_idx_is64;
    const long long* src64 = reinterpret_cast<const long long*>(src);
    const long long* dst64 = reinterpret_cast<const long long*>(dst);
    const int* src32 = reinterpret_cast<const int*>(src);
    const int* dst32 = reinterpret_cast<const int*>(dst);

    for (int q = gw; q < noct; q += nw) {
        const int ebase = q * 8 + sub * 4;

        // --- All 8 index loads first ---
        long s[4], d[4];
        #pragma unroll
        for (int j = 0; j < 4; j++) {
            int e = ebase + j;
            if (e < E) {
                if (is64) { s[j] = (long)src64[e]; d[j] = (long)dst64[e]; }
                else      { s[j] = src32[e];       d[j] = dst32[e]; }
            } else { s[j] = 0; d[j] = 0; }
        }

        // --- 8 independent LDG.128 gathers, issued back-to-back ---
        uint4 av[4], bv[4];
        #pragma unroll
        for (int j = 0; j < 4; j++) {
            av[j] = reinterpret_cast<const uint4*>(g_Ph + (size_t)s[j] * 256)[l16];
            bv[j] = reinterpret_cast<const uint4*>(g_Ph + (size_t)d[j] * 256 + 128)[l16];
        }

        // --- Compute partials ---
        float acc[4];
        #pragma unroll
        for (int j = 0; j < 4; j++)
            acc[j] = edge_partial(av[j], bv[j], b1lo, b1hi, w2lo, w2hi);

        // --- Shared reduction tree over 16 lanes for all four edges ---
        #pragma unroll
        for (int m = 8; m > 0; m >>= 1) {
            #pragma unroll
            for (int j = 0; j < 4; j++)
                acc[j] += __shfl_xor_sync(0xFFFFFFFFu, acc[j], m);
        }

        if (l16 == 0) {
            #pragma unroll
            for (int j = 0; j < 4; j++) {
                int e = ebase + j;
                if (e < E) out[e] = acc[j] + b2v;
            }
        }
    }
}

// ============================================================
// Launch
// ============================================================
extern "C" void kernel_launch(void* const* d_in, const int* in_sizes, int n_in,
                              void* d_out, int out_size) {
    const float* h   = (const float*)d_in[0];
    const void*  src = d_in[1];
    const void*  dst = d_in[2];
    const float* W1  = (const float*)d_in[3];
    const float* b1  = (const float*)d_in[4];
    const float* W2  = (const float*)d_in[5];
    const float* b2  = (const float*)d_in[6];
    float* out = (float*)d_out;
    const int E = out_size;  // one score per edge
    (void)in_sizes; (void)n_in;

    cudaFuncSetAttribute(precompute_kernel,
                         cudaFuncAttributeMaxDynamicSharedMemorySize, SMEM_BYTES);

    precompute_kernel<<<PGRID, 512, SMEM_BYTES>>>(h, W1);
    detect_kernel<<<1, 32>>>((const int*)src);
    edge_kernel<<<2368, 256>>>(src, dst, b1, W2, b2, out, E);
}